// round 1
// baseline (speedup 1.0000x reference)
#include <cuda_runtime.h>
#include <math.h>

#define Bn 4
#define Hn 1080
#define Wn 1920
#define HWn (Hn * Wn)   // 2073600

// ---------------- scratch (no runtime allocation allowed) ----------------
__device__ __align__(16) float g_diff[Bn * HWn];
__device__ __align__(16) float g_cd  [Bn * HWn];
__device__ __align__(16) float g_gr  [Bn * HWn];
__device__ __align__(16) float g_gt  [Bn * HWn];
__device__ int   g_maxd_i;
__device__ int   g_maxcd_i;
__device__ float g_sum[Bn];
__device__ float g_invd, g_invcd;

// ---------------- K0: zero reduction scalars (graph replays!) ------------
__global__ void k0_init() {
    int t = threadIdx.x;
    if (t == 0) g_maxd_i = 0;
    if (t == 1) g_maxcd_i = 0;
    if (t >= 2 && t < 2 + Bn) g_sum[t - 2] = 0.f;
}

// ---------------- K1: pointwise diff/gray + global reductions ------------
__global__ __launch_bounds__(256) void k1_point(const float* __restrict__ ref,
                                                const float* __restrict__ tgt) {
    const int b = blockIdx.y;
    const int v = blockIdx.x * blockDim.x + threadIdx.x;  // float4 index
    float lmaxd = 0.f, lmaxcd = 0.f, lsum = 0.f;

    if (v < HWn / 4) {
        const float4* R0 = (const float4*)(ref + (size_t)(b * 3 + 0) * HWn);
        const float4* R1 = (const float4*)(ref + (size_t)(b * 3 + 1) * HWn);
        const float4* R2 = (const float4*)(ref + (size_t)(b * 3 + 2) * HWn);
        const float4* T0 = (const float4*)(tgt + (size_t)(b * 3 + 0) * HWn);
        const float4* T1 = (const float4*)(tgt + (size_t)(b * 3 + 1) * HWn);
        const float4* T2 = (const float4*)(tgt + (size_t)(b * 3 + 2) * HWn);

        float4 r0 = R0[v], r1 = R1[v], r2 = R2[v];
        float4 t0 = T0[v], t1 = T1[v], t2 = T2[v];
        float4 D, C, GR, GT;

#define LANE(c)                                                               \
        {                                                                     \
            float d0 = r0.c - t0.c, d1 = r1.c - t1.c, d2 = r2.c - t2.c;       \
            float df = sqrtf(d0 * d0 + d1 * d1 + d2 * d2);                    \
            float cd = (fabsf(d0) + fabsf(d1) + fabsf(d2)) * (1.f / 3.f);     \
            D.c = df; C.c = cd;                                               \
            GR.c = 0.299f * r0.c + 0.587f * r1.c + 0.114f * r2.c;             \
            GT.c = 0.299f * t0.c + 0.587f * t1.c + 0.114f * t2.c;             \
            lmaxd = fmaxf(lmaxd, df); lmaxcd = fmaxf(lmaxcd, cd);             \
            lsum += df;                                                       \
        }
        LANE(x) LANE(y) LANE(z) LANE(w)
#undef LANE

        ((float4*)(g_diff + (size_t)b * HWn))[v] = D;
        ((float4*)(g_cd   + (size_t)b * HWn))[v] = C;
        ((float4*)(g_gr   + (size_t)b * HWn))[v] = GR;
        ((float4*)(g_gt   + (size_t)b * HWn))[v] = GT;
    }

    // warp reduce
    #pragma unroll
    for (int o = 16; o > 0; o >>= 1) {
        lmaxd  = fmaxf(lmaxd,  __shfl_xor_sync(0xffffffffu, lmaxd,  o));
        lmaxcd = fmaxf(lmaxcd, __shfl_xor_sync(0xffffffffu, lmaxcd, o));
        lsum  +=               __shfl_xor_sync(0xffffffffu, lsum,   o);
    }
    __shared__ float smx[8], smc[8], sms[8];
    const int lane = threadIdx.x & 31, wid = threadIdx.x >> 5;
    if (lane == 0) { smx[wid] = lmaxd; smc[wid] = lmaxcd; sms[wid] = lsum; }
    __syncthreads();
    if (threadIdx.x == 0) {
        float mx = smx[0], mc = smc[0], s = sms[0];
        #pragma unroll
        for (int i = 1; i < 8; i++) {
            mx = fmaxf(mx, smx[i]); mc = fmaxf(mc, smc[i]); s += sms[i];
        }
        // non-negative floats: int-compare order == float order
        atomicMax(&g_maxd_i,  __float_as_int(mx));
        atomicMax(&g_maxcd_i, __float_as_int(mc));
        atomicAdd(&g_sum[b], s);
    }
}

// ---------------- K2: score + inverse normalizers ------------------------
__global__ void k2_score(float* __restrict__ out) {
    const int t = threadIdx.x;
    const float invd  = 1.f / (__int_as_float(g_maxd_i)  + 1e-12f);
    const float invcd = 1.f / (__int_as_float(g_maxcd_i) + 1e-12f);
    if (t == 0) { g_invd = invd; g_invcd = invcd; }
    if (t < Bn) {
        float m = g_sum[t] * (1.f / (float)HWn) * invd;   // anomaly.mean over batch t
        out[t] = fminf(fmaxf(1.f - m, 0.f), 1.f);
    }
}

// ---------------- K3: fused stencils + diagnostic write -------------------
// 32x32 tile, 32x8 threads, 4 rows per thread.
__global__ __launch_bounds__(256) void k3_stencil(float* __restrict__ diag) {
    const int b  = blockIdx.z;
    const int x0 = blockIdx.x * 32;
    const int y0 = blockIdx.y * 32;

    __shared__ float sgr[38][40], sgt[38][40];       // gray tiles, halo 3
    __shared__ float hr[38][32],  ht[38][32];        // horizontal 7-sums
    __shared__ float sagx[36][37], sagy[36][37];     // |gx|, |gy| over halo-2 region
    __shared__ float sedge[36][37];                  // edge bits over halo-2 region
    __shared__ float hmax[36][32];                   // horizontal 5-max of edges

    const int tid = threadIdx.y * 32 + threadIdx.x;
    const float* gr = g_gr + (size_t)b * HWn;
    const float* gt = g_gt + (size_t)b * HWn;

    // stage 1: load gray tiles (zero-padded)
    for (int p = tid; p < 38 * 38; p += 256) {
        int j = p / 38, i = p - j * 38;
        int y = y0 - 3 + j, x = x0 - 3 + i;
        bool in = (y >= 0) & (y < Hn) & (x >= 0) & (x < Wn);
        int idx = y * Wn + x;
        sgr[j][i] = in ? __ldg(gr + idx) : 0.f;
        sgt[j][i] = in ? __ldg(gt + idx) : 0.f;
    }
    __syncthreads();

    // stage 2a: horizontal 7-sums for separable box
    for (int p = tid; p < 38 * 32; p += 256) {
        int j = p >> 5, i = p & 31;
        float sr = 0.f, st = 0.f;
        #pragma unroll
        for (int k = 0; k < 7; k++) { sr += sgr[j][i + k]; st += sgt[j][i + k]; }
        hr[j][i] = sr; ht[j][i] = st;
    }
    // stage 2b: sobel + edge map over halo-2 region (rel pos -2..33)
    for (int p = tid; p < 36 * 36; p += 256) {
        int j = p / 36, i = p - j * 36;
        // sgt center for rel pos (j-2, i-2) is sgt[j+1][i+1]
        float a00 = sgt[j][i],     a01 = sgt[j][i + 1],     a02 = sgt[j][i + 2];
        float a10 = sgt[j + 1][i],                          a12 = sgt[j + 1][i + 2];
        float a20 = sgt[j + 2][i], a21 = sgt[j + 2][i + 1], a22 = sgt[j + 2][i + 2];
        float gxv = (a02 - a00) + 2.f * (a12 - a10) + (a22 - a20);
        float gyv = (a20 - a00) + 2.f * (a21 - a01) + (a22 - a02);
        float ax = fabsf(gxv), ay = fabsf(gyv);
        int y = y0 - 2 + j, x = x0 - 2 + i;
        bool in = (y >= 0) & (y < Hn) & (x >= 0) & (x < Wn);
        float e = (in && (sqrtf(gxv * gxv + gyv * gyv) > 0.15f)) ? 1.f : 0.f;
        sagx[j][i] = ax; sagy[j][i] = ay; sedge[j][i] = e;
    }
    __syncthreads();

    // stage 3: horizontal 5-max for separable dilation
    for (int p = tid; p < 36 * 32; p += 256) {
        int j = p >> 5, i = p & 31;
        float m = sedge[j][i];
        #pragma unroll
        for (int k = 1; k < 5; k++) m = fmaxf(m, sedge[j][i + k]);
        hmax[j][i] = m;
    }
    __syncthreads();

    // stage 4: per-pixel outputs
    const float invd  = g_invd;
    const float invcd = g_invcd;
    const float* diffp = g_diff + (size_t)b * HWn;
    const float* cdp   = g_cd   + (size_t)b * HWn;
    float* o_an = diag + ((size_t)b * 5 + 0) * HWn;
    float* o_cm = diag + ((size_t)b * 5 + 1) * HWn;
    float* o_ss = diag + ((size_t)b * 5 + 2) * HWn;
    float* o_bl = diag + ((size_t)b * 5 + 3) * HWn;
    float* o_ri = diag + ((size_t)b * 5 + 4) * HWn;

    const int x = threadIdx.x;
    const int gx = x0 + x;
    #pragma unroll
    for (int r = 0; r < 4; r++) {
        const int y  = threadIdx.y + r * 8;
        const int gy = y0 + y;
        if (gy >= Hn || gx >= Wn) continue;

        // vertical 7-sum -> box means
        float sr = 0.f, st = 0.f;
        #pragma unroll
        for (int k = 0; k < 7; k++) { sr += hr[y + k][x]; st += ht[y + k][x]; }
        float mu_r = sr * (1.f / 49.f), mu_t = st * (1.f / 49.f);
        float ssim = (2.f * mu_r * mu_t + 1e-4f) / (mu_r * mu_r + mu_t * mu_t + 1e-4f);

        float ax = sagx[y + 2][x + 2];
        float ay = sagy[y + 2][x + 2];
        float e  = sedge[y + 2][x + 2];

        float blk = ((gx & 7) == 0) ? ax : 0.f;
        if ((gy & 7) == 0) blk = fmaxf(blk, ay);
        blk = (blk > 0.05f) ? 1.f : 0.f;

        // vertical 5-max -> dilated edges
        float dil = hmax[y][x];
        #pragma unroll
        for (int k = 1; k < 5; k++) dil = fmaxf(dil, hmax[y + k][x]);

        const int idx = gy * Wn + gx;
        float an   = diffp[idx] * invd;
        float cm   = cdp[idx]   * invcd;
        float ring = fmaxf(dil - e, 0.f) * an;

        o_an[idx] = an;
        o_cm[idx] = cm;
        o_ss[idx] = ssim;
        o_bl[idx] = blk;
        o_ri[idx] = ring;
    }
}

// ---------------- launch ---------------------------------------------------
extern "C" void kernel_launch(void* const* d_in, const int* in_sizes, int n_in,
                              void* d_out, int out_size) {
    const float* ref = (const float*)d_in[0];
    const float* tgt = (const float*)d_in[1];
    float* out = (float*)d_out;   // [0..3] = score, [4..] = diagnostic (B,5,H,W)

    k0_init<<<1, 32>>>();

    dim3 g1((HWn / 4 + 255) / 256, Bn);
    k1_point<<<g1, 256>>>(ref, tgt);

    k2_score<<<1, 32>>>(out);

    dim3 g3((Wn + 31) / 32, (Hn + 31) / 32, Bn);
    dim3 b3(32, 8);
    k3_stencil<<<g3, b3>>>(out + Bn);
}

// round 2
// speedup vs baseline: 1.0515x; 1.0515x over previous
#include <cuda_runtime.h>
#include <math.h>

#define Bn 4
#define Hn 1080
#define Wn 1920
#define HWn (Hn * Wn)   // 2073600

// ---------------- scratch (no runtime allocation allowed) ----------------
__device__ __align__(16) float g_diff[Bn * HWn];
__device__ __align__(16) float g_cd  [Bn * HWn];
__device__ __align__(16) float g_gr  [Bn * HWn];
__device__ __align__(16) float g_gt  [Bn * HWn];
__device__ int   g_maxd_i;
__device__ int   g_maxcd_i;
__device__ float g_sum[Bn];
__device__ float g_invd, g_invcd;

// ---------------- K0: zero reduction scalars (graph replays!) ------------
__global__ void k0_init() {
    int t = threadIdx.x;
    if (t == 0) g_maxd_i = 0;
    if (t == 1) g_maxcd_i = 0;
    if (t >= 2 && t < 2 + Bn) g_sum[t - 2] = 0.f;
}

// ---------------- K1: pointwise diff/gray + global reductions ------------
__global__ __launch_bounds__(256) void k1_point(const float* __restrict__ ref,
                                                const float* __restrict__ tgt) {
    const int b = blockIdx.y;
    const int v = blockIdx.x * blockDim.x + threadIdx.x;  // float4 index
    float lmaxd = 0.f, lmaxcd = 0.f, lsum = 0.f;

    if (v < HWn / 4) {
        const float4* R0 = (const float4*)(ref + (size_t)(b * 3 + 0) * HWn);
        const float4* R1 = (const float4*)(ref + (size_t)(b * 3 + 1) * HWn);
        const float4* R2 = (const float4*)(ref + (size_t)(b * 3 + 2) * HWn);
        const float4* T0 = (const float4*)(tgt + (size_t)(b * 3 + 0) * HWn);
        const float4* T1 = (const float4*)(tgt + (size_t)(b * 3 + 1) * HWn);
        const float4* T2 = (const float4*)(tgt + (size_t)(b * 3 + 2) * HWn);

        float4 r0 = R0[v], r1 = R1[v], r2 = R2[v];
        float4 t0 = T0[v], t1 = T1[v], t2 = T2[v];
        float4 D, C, GR, GT;

#define LANE(c)                                                               \
        {                                                                     \
            float d0 = r0.c - t0.c, d1 = r1.c - t1.c, d2 = r2.c - t2.c;       \
            float df = sqrtf(d0 * d0 + d1 * d1 + d2 * d2);                    \
            float cd = (fabsf(d0) + fabsf(d1) + fabsf(d2)) * (1.f / 3.f);     \
            D.c = df; C.c = cd;                                               \
            GR.c = 0.299f * r0.c + 0.587f * r1.c + 0.114f * r2.c;             \
            GT.c = 0.299f * t0.c + 0.587f * t1.c + 0.114f * t2.c;             \
            lmaxd = fmaxf(lmaxd, df); lmaxcd = fmaxf(lmaxcd, cd);             \
            lsum += df;                                                       \
        }
        LANE(x) LANE(y) LANE(z) LANE(w)
#undef LANE

        ((float4*)(g_diff + (size_t)b * HWn))[v] = D;
        ((float4*)(g_cd   + (size_t)b * HWn))[v] = C;
        ((float4*)(g_gr   + (size_t)b * HWn))[v] = GR;
        ((float4*)(g_gt   + (size_t)b * HWn))[v] = GT;
    }

    #pragma unroll
    for (int o = 16; o > 0; o >>= 1) {
        lmaxd  = fmaxf(lmaxd,  __shfl_xor_sync(0xffffffffu, lmaxd,  o));
        lmaxcd = fmaxf(lmaxcd, __shfl_xor_sync(0xffffffffu, lmaxcd, o));
        lsum  +=               __shfl_xor_sync(0xffffffffu, lsum,   o);
    }
    __shared__ float smx[8], smc[8], sms[8];
    const int lane = threadIdx.x & 31, wid = threadIdx.x >> 5;
    if (lane == 0) { smx[wid] = lmaxd; smc[wid] = lmaxcd; sms[wid] = lsum; }
    __syncthreads();
    if (threadIdx.x == 0) {
        float mx = smx[0], mc = smc[0], s = sms[0];
        #pragma unroll
        for (int i = 1; i < 8; i++) {
            mx = fmaxf(mx, smx[i]); mc = fmaxf(mc, smc[i]); s += sms[i];
        }
        atomicMax(&g_maxd_i,  __float_as_int(mx));
        atomicMax(&g_maxcd_i, __float_as_int(mc));
        atomicAdd(&g_sum[b], s);
    }
}

// ---------------- K2: score + inverse normalizers ------------------------
__global__ void k2_score(float* __restrict__ out) {
    const int t = threadIdx.x;
    const float invd  = 1.f / (__int_as_float(g_maxd_i)  + 1e-12f);
    const float invcd = 1.f / (__int_as_float(g_maxcd_i) + 1e-12f);
    if (t == 0) { g_invd = invd; g_invcd = invcd; }
    if (t < Bn) {
        float m = g_sum[t] * (1.f / (float)HWn) * invd;
        out[t] = fminf(fmaxf(1.f - m, 0.f), 1.f);
    }
}

// ---------------- K3: fused stencils + diagnostic write -------------------
// 32x32 output tile, 256 threads (32x8), register sliding windows everywhere.
__global__ __launch_bounds__(256) void k3_stencil(float* __restrict__ diag) {
    const int b  = blockIdx.z;
    const int x0 = blockIdx.x * 32;
    const int y0 = blockIdx.y * 32;

    __shared__ float sgr[38][41], sgt[38][41];   // gray tiles, halo 3, odd stride
    __shared__ float hr [38][33], ht [38][33];   // horizontal 7-sums (center cols)
    __shared__ float sedge[36][37];              // edge bits, halo 2
    __shared__ float hmax[36][33];               // horizontal 5-max (center cols)
    __shared__ float sax[32][5];                 // |gx| at cols {0,8,16,24}
    __shared__ float say[4][33];                 // |gy| at rows {0,8,16,24}

    const int tid = threadIdx.y * 32 + threadIdx.x;
    const float* gr = g_gr + (size_t)b * HWn;
    const float* gt = g_gt + (size_t)b * HWn;

    // ---- stage 1: load gray tiles (zero-padded) ----
    for (int p = tid; p < 38 * 38; p += 256) {
        int j = p / 38, i = p - j * 38;
        int y = y0 - 3 + j, x = x0 - 3 + i;
        bool in = (y >= 0) & (y < Hn) & (x >= 0) & (x < Wn);
        int idx = y * Wn + x;
        sgr[j][i] = in ? __ldg(gr + idx) : 0.f;
        sgt[j][i] = in ? __ldg(gt + idx) : 0.f;
    }
    __syncthreads();

    // ---- stage 2a: horizontal 7-sums, groups of 4 outputs ----
    for (int p = tid; p < 38 * 8; p += 256) {
        int j = p >> 3, g = p & 7;
        int xg = g * 4;                  // output cols xg..xg+3, reads sgr cols xg..xg+9
        float a[10], c[10];
        #pragma unroll
        for (int k = 0; k < 10; k++) { a[k] = sgr[j][xg + k]; c[k] = sgt[j][xg + k]; }
        float sr = a[0] + a[1] + a[2] + a[3] + a[4] + a[5] + a[6];
        float st = c[0] + c[1] + c[2] + c[3] + c[4] + c[5] + c[6];
        hr[j][xg + 0] = sr; ht[j][xg + 0] = st;
        sr += a[7] - a[0]; st += c[7] - c[0];
        hr[j][xg + 1] = sr; ht[j][xg + 1] = st;
        sr += a[8] - a[1]; st += c[8] - c[1];
        hr[j][xg + 2] = sr; ht[j][xg + 2] = st;
        sr += a[9] - a[2]; st += c[9] - c[2];
        hr[j][xg + 3] = sr; ht[j][xg + 3] = st;
    }

    // ---- stage 2b: Sobel + edge map over halo-2 region, groups of 4 ----
    for (int p = tid; p < 36 * 9; p += 256) {
        int j = p / 9, g = p - j * 9;
        int i0 = g * 4;                  // edge cols i0..i0+3, reads sgt cols i0..i0+5
        float r0[6], r1[6], r2[6];
        #pragma unroll
        for (int k = 0; k < 6; k++) {
            r0[k] = sgt[j][i0 + k];
            r1[k] = sgt[j + 1][i0 + k];
            r2[k] = sgt[j + 2][i0 + k];
        }
        #pragma unroll
        for (int q = 0; q < 4; q++) {
            float gxv = (r0[q+2] - r0[q]) + 2.f * (r1[q+2] - r1[q]) + (r2[q+2] - r2[q]);
            float gyv = (r2[q] - r0[q]) + 2.f * (r2[q+1] - r0[q+1]) + (r2[q+2] - r0[q+2]);
            int i  = i0 + q;
            int ye = y0 - 2 + j, xe = x0 - 2 + i;   // global edge coords
            bool in = (ye >= 0) & (ye < Hn) & (xe >= 0) & (xe < Wn);
            float e = (in && (sqrtf(gxv * gxv + gyv * gyv) > 0.15f)) ? 1.f : 0.f;
            sedge[j][i] = e;
            int yl = j - 2, xl = i - 2;             // local center coords
            if (((xl & 7) == 0) & (xl >= 0) & (xl < 32) & (yl >= 0) & (yl < 32))
                sax[yl][xl >> 3] = fabsf(gxv);
            if (((yl & 7) == 0) & (yl >= 0) & (yl < 32) & (xl >= 0) & (xl < 32))
                say[yl >> 3][xl] = fabsf(gyv);
        }
    }
    __syncthreads();

    // ---- stage 3: horizontal 5-max of edges, groups of 4 ----
    for (int p = tid; p < 36 * 8; p += 256) {
        int j = p >> 3, g = p & 7;
        int xg = g * 4;                  // output cols xg..xg+3 read sedge cols xg..xg+7
        float v[8];
        #pragma unroll
        for (int k = 0; k < 8; k++) v[k] = sedge[j][xg + k];
        // window 5 over 8 -> 4 outputs via shared partial maxes
        float m34 = fmaxf(v[3], v[4]);
        float m234 = fmaxf(v[2], m34);
        float m345 = fmaxf(m34, v[5]);
        hmax[j][xg + 0] = fmaxf(fmaxf(v[0], v[1]), m234);
        hmax[j][xg + 1] = fmaxf(v[1], fmaxf(m234, v[5]));
        hmax[j][xg + 2] = fmaxf(v[2], fmaxf(m345, v[6]));
        hmax[j][xg + 3] = fmaxf(fmaxf(m345, v[6]), v[7]);
    }
    __syncthreads();

    // ---- stage 4: per-pixel outputs, 4 consecutive rows per thread ----
    const float invd  = g_invd;
    const float invcd = g_invcd;
    const float* diffp = g_diff + (size_t)b * HWn;
    const float* cdp   = g_cd   + (size_t)b * HWn;
    float* o_an = diag + ((size_t)b * 5 + 0) * HWn;
    float* o_cm = diag + ((size_t)b * 5 + 1) * HWn;
    float* o_ss = diag + ((size_t)b * 5 + 2) * HWn;
    float* o_bl = diag + ((size_t)b * 5 + 3) * HWn;
    float* o_ri = diag + ((size_t)b * 5 + 4) * HWn;

    const int x  = threadIdx.x;
    const int gx = x0 + x;
    const int yb = threadIdx.y * 4;     // rows yb..yb+3

    // vertical 7-sum sliding over hr/ht rows yb..yb+9
    float vr[10], vt[10];
    #pragma unroll
    for (int k = 0; k < 10; k++) { vr[k] = hr[yb + k][x]; vt[k] = ht[yb + k][x]; }
    float mur[4], mut[4];
    {
        float sr = vr[0]+vr[1]+vr[2]+vr[3]+vr[4]+vr[5]+vr[6];
        float st = vt[0]+vt[1]+vt[2]+vt[3]+vt[4]+vt[5]+vt[6];
        mur[0] = sr; mut[0] = st;
        sr += vr[7]-vr[0]; st += vt[7]-vt[0]; mur[1] = sr; mut[1] = st;
        sr += vr[8]-vr[1]; st += vt[8]-vt[1]; mur[2] = sr; mut[2] = st;
        sr += vr[9]-vr[2]; st += vt[9]-vt[2]; mur[3] = sr; mut[3] = st;
    }

    // vertical 5-max over hmax rows yb..yb+7
    float hm[8];
    #pragma unroll
    for (int k = 0; k < 8; k++) hm[k] = hmax[yb + k][x];
    float dil[4];
    {
        float m34 = fmaxf(hm[3], hm[4]);
        float m234 = fmaxf(hm[2], m34);
        float m345 = fmaxf(m34, hm[5]);
        dil[0] = fmaxf(fmaxf(hm[0], hm[1]), m234);
        dil[1] = fmaxf(hm[1], fmaxf(m234, hm[5]));
        dil[2] = fmaxf(hm[2], fmaxf(m345, hm[6]));
        dil[3] = fmaxf(fmaxf(m345, hm[6]), hm[7]);
    }

    float ev[4];
    #pragma unroll
    for (int r = 0; r < 4; r++) ev[r] = sedge[yb + r + 2][x + 2];

    const bool colblk = ((gx & 7) == 0);
    float axv[4];
    #pragma unroll
    for (int r = 0; r < 4; r++) axv[r] = colblk ? sax[yb + r][x >> 3] : 0.f;

    #pragma unroll
    for (int r = 0; r < 4; r++) {
        const int y  = yb + r;
        const int gy = y0 + y;
        if (gy >= Hn) continue;

        float mu_r = mur[r] * (1.f / 49.f), mu_t = mut[r] * (1.f / 49.f);
        float ssim = (2.f * mu_r * mu_t + 1e-4f) / (mu_r * mu_r + mu_t * mu_t + 1e-4f);

        float blk = axv[r];
        if ((y & 7) == 0) blk = fmaxf(blk, say[y >> 3][x]);
        blk = (blk > 0.05f) ? 1.f : 0.f;

        const int idx = gy * Wn + gx;
        float an   = __ldg(diffp + idx) * invd;
        float cm   = __ldg(cdp + idx)   * invcd;
        float ring = fmaxf(dil[r] - ev[r], 0.f) * an;

        o_an[idx] = an;
        o_cm[idx] = cm;
        o_ss[idx] = ssim;
        o_bl[idx] = blk;
        o_ri[idx] = ring;
    }
}

// ---------------- launch ---------------------------------------------------
extern "C" void kernel_launch(void* const* d_in, const int* in_sizes, int n_in,
                              void* d_out, int out_size) {
    const float* ref = (const float*)d_in[0];
    const float* tgt = (const float*)d_in[1];
    float* out = (float*)d_out;

    k0_init<<<1, 32>>>();

    dim3 g1((HWn / 4 + 255) / 256, Bn);
    k1_point<<<g1, 256>>>(ref, tgt);

    k2_score<<<1, 32>>>(out);

    dim3 g3((Wn + 31) / 32, (Hn + 31) / 32, Bn);
    dim3 b3(32, 8);
    k3_stencil<<<g3, b3>>>(out + Bn);
}

// round 3
// speedup vs baseline: 1.1373x; 1.0817x over previous
#include <cuda_runtime.h>
#include <cuda_fp16.h>
#include <math.h>

#define Bn 4
#define Hn 1080
#define Wn 1920
#define HWn (Hn * Wn)   // 2073600

// ---------------- scratch (no runtime allocation allowed) ----------------
__device__ __align__(16) __half g_diff[Bn * HWn];   // fp16: continuous channel
__device__ __align__(16) __half g_cd  [Bn * HWn];   // fp16: continuous channel
__device__ __align__(16) float  g_gr  [Bn * HWn];   // fp32: threshold-sensitive
__device__ __align__(16) float  g_gt  [Bn * HWn];
__device__ int   g_maxd_i;
__device__ int   g_maxcd_i;
__device__ float g_sum[Bn];
__device__ float g_invd, g_invcd;

static __forceinline__ __device__ unsigned h2u(__half2 h) {
    return *reinterpret_cast<unsigned*>(&h);
}

// ---------------- K0: zero reduction scalars (graph replays!) ------------
__global__ void k0_init() {
    int t = threadIdx.x;
    if (t == 0) g_maxd_i = 0;
    if (t == 1) g_maxcd_i = 0;
    if (t >= 2 && t < 2 + Bn) g_sum[t - 2] = 0.f;
}

// ---------------- K1: pointwise diff/gray + global reductions ------------
__global__ __launch_bounds__(256) void k1_point(const float* __restrict__ ref,
                                                const float* __restrict__ tgt) {
    const int b = blockIdx.y;
    const int v = blockIdx.x * blockDim.x + threadIdx.x;  // float4 index
    float lmaxd = 0.f, lmaxcd = 0.f, lsum = 0.f;

    if (v < HWn / 4) {
        const float4* R0 = (const float4*)(ref + (size_t)(b * 3 + 0) * HWn);
        const float4* R1 = (const float4*)(ref + (size_t)(b * 3 + 1) * HWn);
        const float4* R2 = (const float4*)(ref + (size_t)(b * 3 + 2) * HWn);
        const float4* T0 = (const float4*)(tgt + (size_t)(b * 3 + 0) * HWn);
        const float4* T1 = (const float4*)(tgt + (size_t)(b * 3 + 1) * HWn);
        const float4* T2 = (const float4*)(tgt + (size_t)(b * 3 + 2) * HWn);

        float4 r0 = R0[v], r1 = R1[v], r2 = R2[v];
        float4 t0 = T0[v], t1 = T1[v], t2 = T2[v];
        float4 D, C, GR, GT;

#define LANE(c)                                                               \
        {                                                                     \
            float d0 = r0.c - t0.c, d1 = r1.c - t1.c, d2 = r2.c - t2.c;       \
            float df = sqrtf(d0 * d0 + d1 * d1 + d2 * d2);                    \
            float cd = (fabsf(d0) + fabsf(d1) + fabsf(d2)) * (1.f / 3.f);     \
            D.c = df; C.c = cd;                                               \
            GR.c = 0.299f * r0.c + 0.587f * r1.c + 0.114f * r2.c;             \
            GT.c = 0.299f * t0.c + 0.587f * t1.c + 0.114f * t2.c;             \
            lmaxd = fmaxf(lmaxd, df); lmaxcd = fmaxf(lmaxcd, cd);             \
            lsum += df;                                                       \
        }
        LANE(x) LANE(y) LANE(z) LANE(w)
#undef LANE

        uint2 dv, cv;
        dv.x = h2u(__floats2half2_rn(D.x, D.y));
        dv.y = h2u(__floats2half2_rn(D.z, D.w));
        cv.x = h2u(__floats2half2_rn(C.x, C.y));
        cv.y = h2u(__floats2half2_rn(C.z, C.w));
        ((uint2*)(g_diff + (size_t)b * HWn))[v] = dv;
        ((uint2*)(g_cd   + (size_t)b * HWn))[v] = cv;
        ((float4*)(g_gr  + (size_t)b * HWn))[v] = GR;
        ((float4*)(g_gt  + (size_t)b * HWn))[v] = GT;
    }

    #pragma unroll
    for (int o = 16; o > 0; o >>= 1) {
        lmaxd  = fmaxf(lmaxd,  __shfl_xor_sync(0xffffffffu, lmaxd,  o));
        lmaxcd = fmaxf(lmaxcd, __shfl_xor_sync(0xffffffffu, lmaxcd, o));
        lsum  +=               __shfl_xor_sync(0xffffffffu, lsum,   o);
    }
    __shared__ float smx[8], smc[8], sms[8];
    const int lane = threadIdx.x & 31, wid = threadIdx.x >> 5;
    if (lane == 0) { smx[wid] = lmaxd; smc[wid] = lmaxcd; sms[wid] = lsum; }
    __syncthreads();
    if (threadIdx.x == 0) {
        float mx = smx[0], mc = smc[0], s = sms[0];
        #pragma unroll
        for (int i = 1; i < 8; i++) {
            mx = fmaxf(mx, smx[i]); mc = fmaxf(mc, smc[i]); s += sms[i];
        }
        atomicMax(&g_maxd_i,  __float_as_int(mx));
        atomicMax(&g_maxcd_i, __float_as_int(mc));
        atomicAdd(&g_sum[b], s);
    }
}

// ---------------- K2: score + inverse normalizers ------------------------
__global__ void k2_score(float* __restrict__ out) {
    const int t = threadIdx.x;
    const float invd  = 1.f / (__int_as_float(g_maxd_i)  + 1e-12f);
    const float invcd = 1.f / (__int_as_float(g_maxcd_i) + 1e-12f);
    if (t == 0) { g_invd = invd; g_invcd = invcd; }
    if (t < Bn) {
        float m = g_sum[t] * (1.f / (float)HWn) * invd;
        out[t] = fminf(fmaxf(1.f - m, 0.f), 1.f);
    }
}

// ---------------- K3: fused stencils + diagnostic write -------------------
// 32x32 output tile, 256 threads (32x8). smem: 28.4KB (hmax aliased onto sgr).
__global__ __launch_bounds__(256, 7) void k3_stencil(float* __restrict__ diag) {
    const int b  = blockIdx.z;
    const int x0 = blockIdx.x * 32;
    const int y0 = blockIdx.y * 32;

    // region1 holds sgr during stages 1-2, then hmax during stages 3-4.
    __shared__ __align__(16) float region1[38 * 39];
    float (*sgr)[39]  = reinterpret_cast<float(*)[39]>(region1);
    float (*hmax)[33] = reinterpret_cast<float(*)[33]>(region1);  // 36*33 <= 38*39
    __shared__ float sgt[38][39];
    __shared__ float hr [38][33], ht [38][33];
    __shared__ float sedge[36][37];
    __shared__ float sax[32][5];
    __shared__ float say[4][33];

    const int tid = threadIdx.y * 32 + threadIdx.x;
    const float* gr = g_gr + (size_t)b * HWn;
    const float* gt = g_gt + (size_t)b * HWn;

    // ---- stage 1: load gray tiles (zero-padded) ----
    for (int p = tid; p < 38 * 38; p += 256) {
        int j = p / 38, i = p - j * 38;
        int y = y0 - 3 + j, x = x0 - 3 + i;
        bool in = (y >= 0) & (y < Hn) & (x >= 0) & (x < Wn);
        int idx = y * Wn + x;
        sgr[j][i] = in ? __ldg(gr + idx) : 0.f;
        sgt[j][i] = in ? __ldg(gt + idx) : 0.f;
    }
    __syncthreads();

    // ---- stage 2a: horizontal 7-sums, groups of 4 outputs ----
    for (int p = tid; p < 38 * 8; p += 256) {
        int j = p >> 3, g = p & 7;
        int xg = g * 4;
        float a[10], c[10];
        #pragma unroll
        for (int k = 0; k < 10; k++) { a[k] = sgr[j][xg + k]; c[k] = sgt[j][xg + k]; }
        float sr = a[0] + a[1] + a[2] + a[3] + a[4] + a[5] + a[6];
        float st = c[0] + c[1] + c[2] + c[3] + c[4] + c[5] + c[6];
        hr[j][xg + 0] = sr; ht[j][xg + 0] = st;
        sr += a[7] - a[0]; st += c[7] - c[0];
        hr[j][xg + 1] = sr; ht[j][xg + 1] = st;
        sr += a[8] - a[1]; st += c[8] - c[1];
        hr[j][xg + 2] = sr; ht[j][xg + 2] = st;
        sr += a[9] - a[2]; st += c[9] - c[2];
        hr[j][xg + 3] = sr; ht[j][xg + 3] = st;
    }

    // ---- stage 2b: Sobel + edge map over halo-2 region, groups of 4 ----
    for (int p = tid; p < 36 * 9; p += 256) {
        int j = p / 9, g = p - j * 9;
        int i0 = g * 4;
        float r0[6], r1[6], r2[6];
        #pragma unroll
        for (int k = 0; k < 6; k++) {
            r0[k] = sgt[j][i0 + k];
            r1[k] = sgt[j + 1][i0 + k];
            r2[k] = sgt[j + 2][i0 + k];
        }
        #pragma unroll
        for (int q = 0; q < 4; q++) {
            float gxv = (r0[q+2] - r0[q]) + 2.f * (r1[q+2] - r1[q]) + (r2[q+2] - r2[q]);
            float gyv = (r2[q] - r0[q]) + 2.f * (r2[q+1] - r0[q+1]) + (r2[q+2] - r0[q+2]);
            int i  = i0 + q;
            int ye = y0 - 2 + j, xe = x0 - 2 + i;
            bool in = (ye >= 0) & (ye < Hn) & (xe >= 0) & (xe < Wn);
            float e = (in && (sqrtf(gxv * gxv + gyv * gyv) > 0.15f)) ? 1.f : 0.f;
            sedge[j][i] = e;
            int yl = j - 2, xl = i - 2;
            if (((xl & 7) == 0) & (xl >= 0) & (xl < 32) & (yl >= 0) & (yl < 32))
                sax[yl][xl >> 3] = fabsf(gxv);
            if (((yl & 7) == 0) & (yl >= 0) & (yl < 32) & (xl >= 0) & (xl < 32))
                say[yl >> 3][xl] = fabsf(gyv);
        }
    }
    __syncthreads();   // sgr dead from here; region1 becomes hmax

    // ---- stage 3: horizontal 5-max of edges, groups of 4 ----
    for (int p = tid; p < 36 * 8; p += 256) {
        int j = p >> 3, g = p & 7;
        int xg = g * 4;
        float v[8];
        #pragma unroll
        for (int k = 0; k < 8; k++) v[k] = sedge[j][xg + k];
        float m34 = fmaxf(v[3], v[4]);
        float m234 = fmaxf(v[2], m34);
        float m345 = fmaxf(m34, v[5]);
        hmax[j][xg + 0] = fmaxf(fmaxf(v[0], v[1]), m234);
        hmax[j][xg + 1] = fmaxf(v[1], fmaxf(m234, v[5]));
        hmax[j][xg + 2] = fmaxf(v[2], fmaxf(m345, v[6]));
        hmax[j][xg + 3] = fmaxf(fmaxf(m345, v[6]), v[7]);
    }
    __syncthreads();

    // ---- stage 4: per-pixel outputs, 4 consecutive rows per thread ----
    const float invd  = g_invd;
    const float invcd = g_invcd;
    const __half* diffp = g_diff + (size_t)b * HWn;
    const __half* cdp   = g_cd   + (size_t)b * HWn;
    float* o_an = diag + ((size_t)b * 5 + 0) * HWn;
    float* o_cm = diag + ((size_t)b * 5 + 1) * HWn;
    float* o_ss = diag + ((size_t)b * 5 + 2) * HWn;
    float* o_bl = diag + ((size_t)b * 5 + 3) * HWn;
    float* o_ri = diag + ((size_t)b * 5 + 4) * HWn;

    const int x  = threadIdx.x;
    const int gx = x0 + x;
    const int yb = threadIdx.y * 4;

    float vr[10], vt[10];
    #pragma unroll
    for (int k = 0; k < 10; k++) { vr[k] = hr[yb + k][x]; vt[k] = ht[yb + k][x]; }
    float mur[4], mut[4];
    {
        float sr = vr[0]+vr[1]+vr[2]+vr[3]+vr[4]+vr[5]+vr[6];
        float st = vt[0]+vt[1]+vt[2]+vt[3]+vt[4]+vt[5]+vt[6];
        mur[0] = sr; mut[0] = st;
        sr += vr[7]-vr[0]; st += vt[7]-vt[0]; mur[1] = sr; mut[1] = st;
        sr += vr[8]-vr[1]; st += vt[8]-vt[1]; mur[2] = sr; mut[2] = st;
        sr += vr[9]-vr[2]; st += vt[9]-vt[2]; mur[3] = sr; mut[3] = st;
    }

    float hm[8];
    #pragma unroll
    for (int k = 0; k < 8; k++) hm[k] = hmax[yb + k][x];
    float dil[4];
    {
        float m34 = fmaxf(hm[3], hm[4]);
        float m234 = fmaxf(hm[2], m34);
        float m345 = fmaxf(m34, hm[5]);
        dil[0] = fmaxf(fmaxf(hm[0], hm[1]), m234);
        dil[1] = fmaxf(hm[1], fmaxf(m234, hm[5]));
        dil[2] = fmaxf(hm[2], fmaxf(m345, hm[6]));
        dil[3] = fmaxf(fmaxf(m345, hm[6]), hm[7]);
    }

    float ev[4];
    #pragma unroll
    for (int r = 0; r < 4; r++) ev[r] = sedge[yb + r + 2][x + 2];

    const bool colblk = ((gx & 7) == 0);
    float axv[4];
    #pragma unroll
    for (int r = 0; r < 4; r++) axv[r] = colblk ? sax[yb + r][x >> 3] : 0.f;

    #pragma unroll
    for (int r = 0; r < 4; r++) {
        const int y  = yb + r;
        const int gy = y0 + y;
        if (gy >= Hn) continue;

        float mu_r = mur[r] * (1.f / 49.f), mu_t = mut[r] * (1.f / 49.f);
        float ssim = (2.f * mu_r * mu_t + 1e-4f) / (mu_r * mu_r + mu_t * mu_t + 1e-4f);

        float blk = axv[r];
        if ((y & 7) == 0) blk = fmaxf(blk, say[y >> 3][x]);
        blk = (blk > 0.05f) ? 1.f : 0.f;

        const int idx = gy * Wn + gx;
        float an   = __half2float(__ldg(diffp + idx)) * invd;
        float cm   = __half2float(__ldg(cdp   + idx)) * invcd;
        float ring = fmaxf(dil[r] - ev[r], 0.f) * an;

        o_an[idx] = an;
        o_cm[idx] = cm;
        o_ss[idx] = ssim;
        o_bl[idx] = blk;
        o_ri[idx] = ring;
    }
}

// ---------------- launch ---------------------------------------------------
extern "C" void kernel_launch(void* const* d_in, const int* in_sizes, int n_in,
                              void* d_out, int out_size) {
    const float* ref = (const float*)d_in[0];
    const float* tgt = (const float*)d_in[1];
    float* out = (float*)d_out;

    k0_init<<<1, 32>>>();

    dim3 g1((HWn / 4 + 255) / 256, Bn);
    k1_point<<<g1, 256>>>(ref, tgt);

    k2_score<<<1, 32>>>(out);

    dim3 g3((Wn + 31) / 32, (Hn + 31) / 32, Bn);
    dim3 b3(32, 8);
    k3_stencil<<<g3, b3>>>(out + Bn);
}